// round 3
// baseline (speedup 1.0000x reference)
#include <cuda_runtime.h>
#include <cuda_bf16.h>

#define HW   256
#define CTOT 96
#define TILE 32
#define HALO 4
#define IND  40        // TILE + 2*HALO
#define INSTRIDE 44    // padded row stride (multiple of 4 for 16B-aligned STS.128)
#define BPD  34        // TILE + 2 (3x3 conv halo 1)

__device__ __forceinline__ float cntk(int g, int p) {
    int lo = g - p; if (lo < 0) lo = 0;
    int hi = g + p; if (hi > HW - 1) hi = HW - 1;
    return (float)(hi - lo + 1);
}

__device__ __forceinline__ float silu_bn(float acc, float inv, float bias) {
    float yv = fmaf(acc, inv, bias);
    return yv * __frcp_rn(1.f + __expf(-yv));
}

__global__ __launch_bounds__(256) void trifreq_kernel(
    const float* __restrict__ x,
    const float* __restrict__ w_lo,
    const float* __restrict__ w_mf,
    const float* __restrict__ w_hf,
    const float* __restrict__ bn_gamma,
    const float* __restrict__ bn_beta,
    const float* __restrict__ bn_mean,
    const float* __restrict__ bn_var,
    float* __restrict__ out)
{
    __shared__ __align__(16) float IN[IND][INSTRIDE];
    __shared__ float H7[IND][IND + 1];
    __shared__ float H3[IND][IND + 1];
    __shared__ float BP[BPD][BPD + 2];

    const int plane = blockIdx.y;
    const int b = plane / CTOT;
    const int c = plane % CTOT;
    const int tile = blockIdx.x;
    const int tx0 = (tile & 7) * TILE;
    const int ty0 = (tile >> 3) * TILE;
    const int tid = threadIdx.x;

    const int g = c >> 5;        // 0=lo, 1=mf, 2=hf
    const int j = c & 31;        // index within group
    const int o = j * 3 + g;     // shuffled output channel

    const float* xp = x + (size_t)(b * CTOT + c) * HW * HW;

    // ---- vectorized load: 40x40 tile (halo 4), zero-padded outside image ----
    // 10 float4 per row, 40 rows = 400 vector loads. tx0-4 is a multiple of 4,
    // so interior vectors are 16B-aligned in gmem; smem row stride 44 floats
    // keeps STS 16B-aligned.
    for (int idx = tid; idx < IND * 10; idx += 256) {
        int r = idx / 10, q = idx % 10;
        int gy  = ty0 - HALO + r;
        int gx0 = tx0 - HALO + q * 4;
        float4 v = make_float4(0.f, 0.f, 0.f, 0.f);
        if ((unsigned)gy < HW) {
            const float* row = xp + gy * HW;
            if (gx0 >= 0 && gx0 + 3 < HW) {
                v = *reinterpret_cast<const float4*>(row + gx0);
            } else {
                float* ve = reinterpret_cast<float*>(&v);
                #pragma unroll
                for (int e = 0; e < 4; e++) {
                    int gx = gx0 + e;
                    if ((unsigned)gx < HW) ve[e] = row[gx];
                }
            }
        }
        *reinterpret_cast<float4*>(&IN[r][q * 4]) = v;
    }
    __syncthreads();

    const float inv  = bn_gamma[o] * rsqrtf(bn_var[o] + 1e-5f);
    const float bias = bn_beta[o] - bn_mean[o] * inv;
    float* outp = out + (size_t)(b * CTOT + o) * HW * HW;

    if (g == 0) {
        // ---- low band: 5x5 dwconv directly on IN ----
        float wv[25];
        #pragma unroll
        for (int i = 0; i < 25; i++) wv[i] = __ldg(&w_lo[j * 25 + i]);
        for (int pid = tid; pid < TILE * TILE; pid += 256) {
            int ly = pid >> 5, lx = pid & 31;
            int R = ly + HALO, Cc = lx + HALO;
            float acc = 0.f;
            #pragma unroll
            for (int dy = 0; dy < 5; dy++)
                #pragma unroll
                for (int dx = 0; dx < 5; dx++)
                    acc = fmaf(IN[R - 2 + dy][Cc - 2 + dx], wv[dy * 5 + dx], acc);
            outp[(ty0 + ly) * HW + tx0 + lx] = silu_bn(acc, inv, bias);
        }
    } else if (g == 1) {
        // ---- mid band: (avgpool3 - avgpool7) then 3x3 dwconv ----
        // horizontal box sums at IN-cols [3, 36], all 40 rows
        for (int idx = tid; idx < IND * BPD; idx += 256) {
            int r = idx / BPD, cc = idx % BPD + 3;
            float s7 = 0.f;
            #pragma unroll
            for (int d = -3; d <= 3; d++) s7 += IN[r][cc + d];
            H7[r][cc] = s7;
            H3[r][cc] = IN[r][cc - 1] + IN[r][cc] + IN[r][cc + 1];
        }
        __syncthreads();
        // vertical sums -> band-pass values on [tile-1, tile+32]
        for (int idx = tid; idx < BPD * BPD; idx += 256) {
            int i = idx / BPD, jj = idx % BPD;
            int gy = ty0 - 1 + i;
            int gx = tx0 - 1 + jj;
            float bp = 0.f;
            if ((unsigned)gy < HW && (unsigned)gx < HW) {
                int R = i + 3, Cc = jj + 3;
                float v7 = 0.f;
                #pragma unroll
                for (int d = -3; d <= 3; d++) v7 += H7[R + d][Cc];
                float v3 = H3[R - 1][Cc] + H3[R][Cc] + H3[R + 1][Cc];
                float c3 = cntk(gx, 1) * cntk(gy, 1);
                float c7 = cntk(gx, 3) * cntk(gy, 3);
                bp = v3 / c3 - v7 / c7;
            }
            BP[i][jj] = bp;
        }
        __syncthreads();
        float wv[9];
        #pragma unroll
        for (int i = 0; i < 9; i++) wv[i] = __ldg(&w_mf[j * 9 + i]);
        for (int pid = tid; pid < TILE * TILE; pid += 256) {
            int ly = pid >> 5, lx = pid & 31;
            float acc = 0.f;
            #pragma unroll
            for (int dy = 0; dy < 3; dy++)
                #pragma unroll
                for (int dx = 0; dx < 3; dx++)
                    acc = fmaf(BP[ly + dy][lx + dx], wv[dy * 3 + dx], acc);
            outp[(ty0 + ly) * HW + tx0 + lx] = silu_bn(acc, inv, bias);
        }
    } else {
        // ---- high band: (x - avgpool3) then 3x3 dwconv ----
        for (int idx = tid; idx < BPD * BPD; idx += 256) {
            int i = idx / BPD, jj = idx % BPD;
            int gy = ty0 - 1 + i;
            int gx = tx0 - 1 + jj;
            float hp = 0.f;
            if ((unsigned)gy < HW && (unsigned)gx < HW) {
                int R = i + 3, Cc = jj + 3;
                float s3 = 0.f;
                #pragma unroll
                for (int dy = -1; dy <= 1; dy++)
                    #pragma unroll
                    for (int dx = -1; dx <= 1; dx++)
                        s3 += IN[R + dy][Cc + dx];
                float c3 = cntk(gx, 1) * cntk(gy, 1);
                hp = IN[R][Cc] - s3 / c3;
            }
            BP[i][jj] = hp;
        }
        __syncthreads();
        float wv[9];
        #pragma unroll
        for (int i = 0; i < 9; i++) wv[i] = __ldg(&w_hf[j * 9 + i]);
        for (int pid = tid; pid < TILE * TILE; pid += 256) {
            int ly = pid >> 5, lx = pid & 31;
            float acc = 0.f;
            #pragma unroll
            for (int dy = 0; dy < 3; dy++)
                #pragma unroll
                for (int dx = 0; dx < 3; dx++)
                    acc = fmaf(BP[ly + dy][lx + dx], wv[dy * 3 + dx], acc);
            outp[(ty0 + ly) * HW + tx0 + lx] = silu_bn(acc, inv, bias);
        }
    }
}

extern "C" void kernel_launch(void* const* d_in, const int* in_sizes, int n_in,
                              void* d_out, int out_size) {
    const float* x        = (const float*)d_in[0];
    const float* w_lo     = (const float*)d_in[1];
    const float* w_mf     = (const float*)d_in[2];
    const float* w_hf     = (const float*)d_in[3];
    const float* bn_gamma = (const float*)d_in[4];
    const float* bn_beta  = (const float*)d_in[5];
    const float* bn_mean  = (const float*)d_in[6];
    const float* bn_var   = (const float*)d_in[7];
    float* out = (float*)d_out;

    dim3 grid((HW / TILE) * (HW / TILE), 8 * CTOT);
    trifreq_kernel<<<grid, 256>>>(x, w_lo, w_mf, w_hf,
                                  bn_gamma, bn_beta, bn_mean, bn_var, out);
}

// round 10
// speedup vs baseline: 1.1310x; 1.1310x over previous
#include <cuda_runtime.h>
#include <cuda_bf16.h>

#define HW   256
#define CTOT 96
#define TILE 32
#define HALO 4
#define IND  40        // TILE + 2*HALO
#define INSTRIDE 44    // IN row stride (multiple of 4, 16B-aligned rows)
#define HSTRIDE 40     // H7/H3 row stride
#define BPD  34        // TILE + 2 (3x3 conv halo 1)
#define BPSTRIDE 36    // BP row stride

__device__ __forceinline__ float cntk(int g, int p) {
    int lo = g - p; if (lo < 0) lo = 0;
    int hi = g + p; if (hi > HW - 1) hi = HW - 1;
    return (float)(hi - lo + 1);
}

__device__ __forceinline__ float silu_bn(float acc, float inv, float bias) {
    float yv = fmaf(acc, inv, bias);
    return yv * __frcp_rn(1.f + __expf(-yv));
}

__global__ __launch_bounds__(256, 6) void trifreq_kernel(
    const float* __restrict__ x,
    const float* __restrict__ w_lo,
    const float* __restrict__ w_mf,
    const float* __restrict__ w_hf,
    const float* __restrict__ bn_gamma,
    const float* __restrict__ bn_beta,
    const float* __restrict__ bn_mean,
    const float* __restrict__ bn_var,
    float* __restrict__ out)
{
    __shared__ __align__(16) float IN[IND][INSTRIDE];
    __shared__ __align__(16) float H7[IND][HSTRIDE];
    __shared__ __align__(16) float H3[IND][HSTRIDE];
    __shared__ __align__(16) float BP[BPD][BPSTRIDE];

    const int plane = blockIdx.y;
    const int b = plane / CTOT;
    const int c = plane % CTOT;
    const int tile = blockIdx.x;
    const int tx0 = (tile & 7) * TILE;
    const int ty0 = (tile >> 3) * TILE;
    const int tid = threadIdx.x;

    const int g = c >> 5;        // 0=lo, 1=mf, 2=hf
    const int j = c & 31;        // index within group
    const int o = j * 3 + g;     // shuffled output channel

    const float* xp = x + (size_t)(b * CTOT + c) * HW * HW;

    // ---- vectorized load: 40x40 tile (halo 4), zero-padded outside image ----
    for (int idx = tid; idx < IND * 10; idx += 256) {
        int r = idx / 10, q = idx % 10;
        int gy  = ty0 - HALO + r;
        int gx0 = tx0 - HALO + q * 4;
        float4 v = make_float4(0.f, 0.f, 0.f, 0.f);
        if ((unsigned)gy < HW) {
            const float* row = xp + gy * HW;
            if (gx0 >= 0 && gx0 + 3 < HW) {
                v = *reinterpret_cast<const float4*>(row + gx0);
            } else {
                float* ve = reinterpret_cast<float*>(&v);
                #pragma unroll
                for (int e = 0; e < 4; e++) {
                    int gx = gx0 + e;
                    if ((unsigned)gx < HW) ve[e] = row[gx];
                }
            }
        }
        *reinterpret_cast<float4*>(&IN[r][q * 4]) = v;
    }
    __syncthreads();

    const float inv  = bn_gamma[o] * rsqrtf(bn_var[o] + 1e-5f);
    const float bias = bn_beta[o] - bn_mean[o] * inv;
    float* outp = out + (size_t)(b * CTOT + o) * HW * HW;

    // compute-phase thread mapping: 4 horizontal pixels per thread
    const int lq  = tid & 7;
    const int lx4 = lq * 4;       // output cols lx4..lx4+3
    const int ly  = tid >> 3;     // output row 0..31

    if (g == 0) {
        // ---- low band: 5x5 dwconv on IN via register sliding window ----
        float wv[25];
        #pragma unroll
        for (int i = 0; i < 25; i++) wv[i] = __ldg(&w_lo[j * 25 + i]);
        float a0 = 0.f, a1 = 0.f, a2 = 0.f, a3 = 0.f;
        #pragma unroll
        for (int dy = 0; dy < 5; dy++) {
            const float* rp = &IN[ly + 2 + dy][lx4];
            float4 va = *reinterpret_cast<const float4*>(rp);
            float4 vb = *reinterpret_cast<const float4*>(rp + 4);
            float4 vc = *reinterpret_cast<const float4*>(rp + 8);
            float f[12] = {va.x, va.y, va.z, va.w, vb.x, vb.y, vb.z, vb.w,
                           vc.x, vc.y, vc.z, vc.w};
            #pragma unroll
            for (int t = 0; t < 5; t++) {
                float w = wv[dy * 5 + t];
                a0 = fmaf(f[2 + t], w, a0);
                a1 = fmaf(f[3 + t], w, a1);
                a2 = fmaf(f[4 + t], w, a2);
                a3 = fmaf(f[5 + t], w, a3);
            }
        }
        float4 r;
        r.x = silu_bn(a0, inv, bias);
        r.y = silu_bn(a1, inv, bias);
        r.z = silu_bn(a2, inv, bias);
        r.w = silu_bn(a3, inv, bias);
        *reinterpret_cast<float4*>(outp + (ty0 + ly) * HW + tx0 + lx4) = r;
    } else if (g == 1) {
        // ---- mid band: (avgpool3 - avgpool7) then 3x3 dwconv ----
        // Stage A: horizontal sums H7/H3, 40 rows x 10 col-groups
        for (int it = tid; it < IND * 10; it += 256) {
            int r = it / 10, q = it % 10;
            int c0 = q * 4;
            float f[12];
            if (q >= 1) {
                float4 v = *reinterpret_cast<const float4*>(&IN[r][c0 - 4]);
                f[0] = v.x; f[1] = v.y; f[2] = v.z; f[3] = v.w;
            } else { f[0] = f[1] = f[2] = f[3] = 0.f; }
            { float4 v = *reinterpret_cast<const float4*>(&IN[r][c0]);
              f[4] = v.x; f[5] = v.y; f[6] = v.z; f[7] = v.w; }
            if (q <= 8) {
                float4 v = *reinterpret_cast<const float4*>(&IN[r][c0 + 4]);
                f[8] = v.x; f[9] = v.y; f[10] = v.z; f[11] = v.w;
            } else { f[8] = f[9] = f[10] = f[11] = 0.f; }
            // H7[c0+o] = sum f[o+1 .. o+7]; running sum
            float s = f[1] + f[2] + f[3] + f[4] + f[5] + f[6] + f[7];
            float4 h7, h3;
            h7.x = s; s += f[8]  - f[1]; h7.y = s;
                      s += f[9]  - f[2]; h7.z = s;
                      s += f[10] - f[3]; h7.w = s;
            h3.x = f[3] + f[4] + f[5];
            h3.y = f[4] + f[5] + f[6];
            h3.z = f[5] + f[6] + f[7];
            h3.w = f[6] + f[7] + f[8];
            *reinterpret_cast<float4*>(&H7[r][c0]) = h7;
            *reinterpret_cast<float4*>(&H3[r][c0]) = h3;
        }
        __syncthreads();
        // Stage B: vertical sums + normalize -> BP, 34 rows x 9 col-groups
        for (int it = tid; it < BPD * 9; it += 256) {
            int i = it / 9, q = it % 9;
            int c0 = q * 4;           // H col base; h[t] <-> H col c0+t
            float v7[8] = {0,0,0,0,0,0,0,0};
            #pragma unroll
            for (int d = 0; d < 7; d++) {
                float4 va = *reinterpret_cast<const float4*>(&H7[i + d][c0]);
                float4 vb = *reinterpret_cast<const float4*>(&H7[i + d][c0 + 4]);
                v7[0] += va.x; v7[1] += va.y; v7[2] += va.z; v7[3] += va.w;
                v7[4] += vb.x; v7[5] += vb.y; v7[6] += vb.z; v7[7] += vb.w;
            }
            float v3[8] = {0,0,0,0,0,0,0,0};
            #pragma unroll
            for (int d = 2; d < 5; d++) {
                float4 va = *reinterpret_cast<const float4*>(&H3[i + d][c0]);
                float4 vb = *reinterpret_cast<const float4*>(&H3[i + d][c0 + 4]);
                v3[0] += va.x; v3[1] += va.y; v3[2] += va.z; v3[3] += va.w;
                v3[4] += vb.x; v3[5] += vb.y; v3[6] += vb.z; v3[7] += vb.w;
            }
            int gy = ty0 - 1 + i;
            float cy3 = cntk(gy, 1), cy7 = cntk(gy, 3);
            float4 bp = make_float4(0.f, 0.f, 0.f, 0.f);
            float* bpe = reinterpret_cast<float*>(&bp);
            if ((unsigned)gy < HW) {
                #pragma unroll
                for (int oo = 0; oo < 4; oo++) {
                    int jj = c0 + oo;           // BP col; Cc = jj+3 -> h idx 3+oo
                    int gx = tx0 - 1 + jj;
                    if ((unsigned)gx < HW) {
                        float r3 = __frcp_rn(cntk(gx, 1) * cy3);
                        float r7 = __frcp_rn(cntk(gx, 3) * cy7);
                        bpe[oo] = v3[3 + oo] * r3 - v7[3 + oo] * r7;
                    }
                }
            }
            *reinterpret_cast<float4*>(&BP[i][c0]) = bp;
        }
        __syncthreads();
        // Stage C: 3x3 conv over BP
        float wv[9];
        #pragma unroll
        for (int i = 0; i < 9; i++) wv[i] = __ldg(&w_mf[j * 9 + i]);
        float a0 = 0.f, a1 = 0.f, a2 = 0.f, a3 = 0.f;
        #pragma unroll
        for (int dy = 0; dy < 3; dy++) {
            float4 va = *reinterpret_cast<const float4*>(&BP[ly + dy][lx4]);
            float4 vb = *reinterpret_cast<const float4*>(&BP[ly + dy][lx4 + 4]);
            float f[8] = {va.x, va.y, va.z, va.w, vb.x, vb.y, vb.z, vb.w};
            #pragma unroll
            for (int t = 0; t < 3; t++) {
                float w = wv[dy * 3 + t];
                a0 = fmaf(f[0 + t], w, a0);
                a1 = fmaf(f[1 + t], w, a1);
                a2 = fmaf(f[2 + t], w, a2);
                a3 = fmaf(f[3 + t], w, a3);
            }
        }
        float4 r;
        r.x = silu_bn(a0, inv, bias);
        r.y = silu_bn(a1, inv, bias);
        r.z = silu_bn(a2, inv, bias);
        r.w = silu_bn(a3, inv, bias);
        *reinterpret_cast<float4*>(outp + (ty0 + ly) * HW + tx0 + lx4) = r;
    } else {
        // ---- high band: (x - avgpool3) then 3x3 dwconv ----
        // Stage A: high-pass -> BP, 34 rows x 9 col-groups
        for (int it = tid; it < BPD * 9; it += 256) {
            int i = it / 9, q = it % 9;
            int jj0 = q * 4;
            // IN rows i+2..i+4, cols jj0..jj0+7  (f[t] <-> IN col jj0+t)
            float4 r0a = *reinterpret_cast<const float4*>(&IN[i + 2][jj0]);
            float4 r0b = *reinterpret_cast<const float4*>(&IN[i + 2][jj0 + 4]);
            float4 r1a = *reinterpret_cast<const float4*>(&IN[i + 3][jj0]);
            float4 r1b = *reinterpret_cast<const float4*>(&IN[i + 3][jj0 + 4]);
            float4 r2a = *reinterpret_cast<const float4*>(&IN[i + 4][jj0]);
            float4 r2b = *reinterpret_cast<const float4*>(&IN[i + 4][jj0 + 4]);
            float s[8], ctr[8];
            s[0] = r0a.x + r1a.x + r2a.x; ctr[0] = r1a.x;
            s[1] = r0a.y + r1a.y + r2a.y; ctr[1] = r1a.y;
            s[2] = r0a.z + r1a.z + r2a.z; ctr[2] = r1a.z;
            s[3] = r0a.w + r1a.w + r2a.w; ctr[3] = r1a.w;
            s[4] = r0b.x + r1b.x + r2b.x; ctr[4] = r1b.x;
            s[5] = r0b.y + r1b.y + r2b.y; ctr[5] = r1b.y;
            s[6] = r0b.z + r1b.z + r2b.z; ctr[6] = r1b.z;
            s[7] = r0b.w + r1b.w + r2b.w; ctr[7] = r1b.w;
            int gy = ty0 - 1 + i;
            float cy3 = cntk(gy, 1);
            float4 bp = make_float4(0.f, 0.f, 0.f, 0.f);
            float* bpe = reinterpret_cast<float*>(&bp);
            if ((unsigned)gy < HW) {
                #pragma unroll
                for (int oo = 0; oo < 4; oo++) {
                    int gx = tx0 - 1 + jj0 + oo;
                    if ((unsigned)gx < HW) {
                        float sum3 = s[oo + 2] + s[oo + 3] + s[oo + 4];
                        float r3 = __frcp_rn(cntk(gx, 1) * cy3);
                        bpe[oo] = ctr[oo + 3] - sum3 * r3;
                    }
                }
            }
            *reinterpret_cast<float4*>(&BP[i][jj0]) = bp;
        }
        __syncthreads();
        // Stage B: 3x3 conv over BP
        float wv[9];
        #pragma unroll
        for (int i = 0; i < 9; i++) wv[i] = __ldg(&w_hf[j * 9 + i]);
        float a0 = 0.f, a1 = 0.f, a2 = 0.f, a3 = 0.f;
        #pragma unroll
        for (int dy = 0; dy < 3; dy++) {
            float4 va = *reinterpret_cast<const float4*>(&BP[ly + dy][lx4]);
            float4 vb = *reinterpret_cast<const float4*>(&BP[ly + dy][lx4 + 4]);
            float f[8] = {va.x, va.y, va.z, va.w, vb.x, vb.y, vb.z, vb.w};
            #pragma unroll
            for (int t = 0; t < 3; t++) {
                float w = wv[dy * 3 + t];
                a0 = fmaf(f[0 + t], w, a0);
                a1 = fmaf(f[1 + t], w, a1);
                a2 = fmaf(f[2 + t], w, a2);
                a3 = fmaf(f[3 + t], w, a3);
            }
        }
        float4 r;
        r.x = silu_bn(a0, inv, bias);
        r.y = silu_bn(a1, inv, bias);
        r.z = silu_bn(a2, inv, bias);
        r.w = silu_bn(a3, inv, bias);
        *reinterpret_cast<float4*>(outp + (ty0 + ly) * HW + tx0 + lx4) = r;
    }
}

extern "C" void kernel_launch(void* const* d_in, const int* in_sizes, int n_in,
                              void* d_out, int out_size) {
    const float* x        = (const float*)d_in[0];
    const float* w_lo     = (const float*)d_in[1];
    const float* w_mf     = (const float*)d_in[2];
    const float* w_hf     = (const float*)d_in[3];
    const float* bn_gamma = (const float*)d_in[4];
    const float* bn_beta  = (const float*)d_in[5];
    const float* bn_mean  = (const float*)d_in[6];
    const float* bn_var   = (const float*)d_in[7];
    float* out = (float*)d_out;

    dim3 grid((HW / TILE) * (HW / TILE), 8 * CTOT);
    trifreq_kernel<<<grid, 256>>>(x, w_lo, w_mf, w_hf,
                                  bn_gamma, bn_beta, bn_mean, bn_var, out);
}

// round 11
// speedup vs baseline: 1.1976x; 1.0589x over previous
#include <cuda_runtime.h>
#include <cuda_bf16.h>

#define HW   256
#define CTOT 96
#define TILE 32
#define HALO 4
#define IND  40        // TILE + 2*HALO
#define INSTRIDE 44    // IN row stride (multiple of 4, 16B-aligned rows)
#define HSTRIDE 40     // H7/H3 row stride
#define BPD  34        // TILE + 2 (3x3 conv halo 1)
#define BPSTRIDE 36    // BP row stride

__device__ __forceinline__ float cntk(int g, int p) {
    int lo = g - p; if (lo < 0) lo = 0;
    int hi = g + p; if (hi > HW - 1) hi = HW - 1;
    return (float)(hi - lo + 1);
}

__device__ __forceinline__ float silu_bn(float acc, float inv, float bias) {
    float yv = fmaf(acc, inv, bias);
    return yv * __frcp_rn(1.f + __expf(-yv));
}

__global__ __launch_bounds__(256, 6) void trifreq_kernel(
    const float* __restrict__ x,
    const float* __restrict__ w_lo,
    const float* __restrict__ w_mf,
    const float* __restrict__ w_hf,
    const float* __restrict__ bn_gamma,
    const float* __restrict__ bn_beta,
    const float* __restrict__ bn_mean,
    const float* __restrict__ bn_var,
    float* __restrict__ out)
{
    __shared__ __align__(16) float IN[IND][INSTRIDE];
    __shared__ __align__(16) float H7[IND][HSTRIDE];
    __shared__ __align__(16) float H3[IND][HSTRIDE];
    __shared__ __align__(16) float BP[BPD][BPSTRIDE];

    const int plane = blockIdx.y;
    const int b = plane / CTOT;
    const int c = plane % CTOT;
    const int tile = blockIdx.x;
    const int tx0 = (tile & 7) * TILE;
    const int ty0 = (tile >> 3) * TILE;
    const int tid = threadIdx.x;

    const int g = c >> 5;        // 0=lo, 1=mf, 2=hf
    const int j = c & 31;        // index within group
    const int o = j * 3 + g;     // shuffled output channel

    const float* xp = x + (size_t)(b * CTOT + c) * HW * HW;

    // ---- vectorized load: 40x40 tile (halo 4), zero-padded outside image ----
    for (int idx = tid; idx < IND * 10; idx += 256) {
        int r = idx / 10, q = idx % 10;
        int gy  = ty0 - HALO + r;
        int gx0 = tx0 - HALO + q * 4;
        float4 v = make_float4(0.f, 0.f, 0.f, 0.f);
        if ((unsigned)gy < HW) {
            const float* row = xp + gy * HW;
            if (gx0 >= 0 && gx0 + 3 < HW) {
                v = *reinterpret_cast<const float4*>(row + gx0);
            } else {
                float* ve = reinterpret_cast<float*>(&v);
                #pragma unroll
                for (int e = 0; e < 4; e++) {
                    int gx = gx0 + e;
                    if ((unsigned)gx < HW) ve[e] = row[gx];
                }
            }
        }
        *reinterpret_cast<float4*>(&IN[r][q * 4]) = v;
    }
    __syncthreads();

    const float inv  = bn_gamma[o] * rsqrtf(bn_var[o] + 1e-5f);
    const float bias = bn_beta[o] - bn_mean[o] * inv;
    float* outp = out + (size_t)(b * CTOT + o) * HW * HW;

    // compute-phase thread mapping: 4 horizontal pixels per thread
    const int lq  = tid & 7;
    const int lx4 = lq * 4;       // output cols lx4..lx4+3
    const int ly  = tid >> 3;     // output row 0..31

    if (g == 0) {
        // ---- low band: 5x5 dwconv on IN via register sliding window ----
        float wv[25];
        #pragma unroll
        for (int i = 0; i < 25; i++) wv[i] = __ldg(&w_lo[j * 25 + i]);
        float a0 = 0.f, a1 = 0.f, a2 = 0.f, a3 = 0.f;
        #pragma unroll
        for (int dy = 0; dy < 5; dy++) {
            const float* rp = &IN[ly + 2 + dy][lx4];
            float4 va = *reinterpret_cast<const float4*>(rp);
            float4 vb = *reinterpret_cast<const float4*>(rp + 4);
            float4 vc = *reinterpret_cast<const float4*>(rp + 8);
            float f[12] = {va.x, va.y, va.z, va.w, vb.x, vb.y, vb.z, vb.w,
                           vc.x, vc.y, vc.z, vc.w};
            #pragma unroll
            for (int t = 0; t < 5; t++) {
                float w = wv[dy * 5 + t];
                a0 = fmaf(f[2 + t], w, a0);
                a1 = fmaf(f[3 + t], w, a1);
                a2 = fmaf(f[4 + t], w, a2);
                a3 = fmaf(f[5 + t], w, a3);
            }
        }
        float4 r;
        r.x = silu_bn(a0, inv, bias);
        r.y = silu_bn(a1, inv, bias);
        r.z = silu_bn(a2, inv, bias);
        r.w = silu_bn(a3, inv, bias);
        *reinterpret_cast<float4*>(outp + (ty0 + ly) * HW + tx0 + lx4) = r;
    } else if (g == 1) {
        // ---- mid band: (avgpool3 - avgpool7) then 3x3 dwconv ----
        // Stage A: horizontal sums H7/H3, 40 rows x 10 col-groups
        for (int it = tid; it < IND * 10; it += 256) {
            int r = it / 10, q = it % 10;
            int c0 = q * 4;
            float f[12];
            if (q >= 1) {
                float4 v = *reinterpret_cast<const float4*>(&IN[r][c0 - 4]);
                f[0] = v.x; f[1] = v.y; f[2] = v.z; f[3] = v.w;
            } else { f[0] = f[1] = f[2] = f[3] = 0.f; }
            { float4 v = *reinterpret_cast<const float4*>(&IN[r][c0]);
              f[4] = v.x; f[5] = v.y; f[6] = v.z; f[7] = v.w; }
            if (q <= 8) {
                float4 v = *reinterpret_cast<const float4*>(&IN[r][c0 + 4]);
                f[8] = v.x; f[9] = v.y; f[10] = v.z; f[11] = v.w;
            } else { f[8] = f[9] = f[10] = f[11] = 0.f; }
            // H7[c0+o] = sum f[o+1 .. o+7]; running sum
            float s = f[1] + f[2] + f[3] + f[4] + f[5] + f[6] + f[7];
            float4 h7, h3;
            h7.x = s; s += f[8]  - f[1]; h7.y = s;
                      s += f[9]  - f[2]; h7.z = s;
                      s += f[10] - f[3]; h7.w = s;
            h3.x = f[3] + f[4] + f[5];
            h3.y = f[4] + f[5] + f[6];
            h3.z = f[5] + f[6] + f[7];
            h3.w = f[6] + f[7] + f[8];
            *reinterpret_cast<float4*>(&H7[r][c0]) = h7;
            *reinterpret_cast<float4*>(&H3[r][c0]) = h3;
        }
        __syncthreads();
        // Stage B: per-column vertical sliding-window sums -> BP
        // 34 cols x 9 row-chunks (4 rows each, last chunk 2)
        for (int it = tid; it < 34 * 9; it += 256) {
            int jj = it % 34;          // BP col
            int ci = it / 34;          // row chunk
            int i0 = ci * 4;
            int iend = (i0 + 4 < BPD) ? (i0 + 4) : BPD;
            int Cc = jj + 3;           // H col
            int gx = tx0 - 1 + jj;
            bool xin = (unsigned)gx < HW;
            float cx3 = cntk(gx, 1), cx7 = cntk(gx, 3);
            float s7 = 0.f, s3 = 0.f;
            #pragma unroll
            for (int d = 0; d < 7; d++) s7 += H7[i0 + d][Cc];
            #pragma unroll
            for (int d = 2; d < 5; d++) s3 += H3[i0 + d][Cc];
            for (int i = i0; i < iend; i++) {
                int gy = ty0 - 1 + i;
                float bp = 0.f;
                if (xin && (unsigned)gy < HW) {
                    float r3 = __frcp_rn(cx3 * cntk(gy, 1));
                    float r7 = __frcp_rn(cx7 * cntk(gy, 3));
                    bp = s3 * r3 - s7 * r7;
                }
                BP[i][jj] = bp;
                if (i + 1 < iend) {
                    s7 += H7[i + 7][Cc] - H7[i][Cc];
                    s3 += H3[i + 5][Cc] - H3[i + 2][Cc];
                }
            }
        }
        __syncthreads();
        // Stage C: 3x3 conv over BP
        float wv[9];
        #pragma unroll
        for (int i = 0; i < 9; i++) wv[i] = __ldg(&w_mf[j * 9 + i]);
        float a0 = 0.f, a1 = 0.f, a2 = 0.f, a3 = 0.f;
        #pragma unroll
        for (int dy = 0; dy < 3; dy++) {
            float4 va = *reinterpret_cast<const float4*>(&BP[ly + dy][lx4]);
            float4 vb = *reinterpret_cast<const float4*>(&BP[ly + dy][lx4 + 4]);
            float f[8] = {va.x, va.y, va.z, va.w, vb.x, vb.y, vb.z, vb.w};
            #pragma unroll
            for (int t = 0; t < 3; t++) {
                float w = wv[dy * 3 + t];
                a0 = fmaf(f[0 + t], w, a0);
                a1 = fmaf(f[1 + t], w, a1);
                a2 = fmaf(f[2 + t], w, a2);
                a3 = fmaf(f[3 + t], w, a3);
            }
        }
        float4 r;
        r.x = silu_bn(a0, inv, bias);
        r.y = silu_bn(a1, inv, bias);
        r.z = silu_bn(a2, inv, bias);
        r.w = silu_bn(a3, inv, bias);
        *reinterpret_cast<float4*>(outp + (ty0 + ly) * HW + tx0 + lx4) = r;
    } else {
        // ---- high band: (x - avgpool3) then 3x3 dwconv ----
        // Stage A: high-pass -> BP, 34 rows x 9 col-groups
        for (int it = tid; it < BPD * 9; it += 256) {
            int i = it / 9, q = it % 9;
            int jj0 = q * 4;
            // IN rows i+2..i+4, cols jj0..jj0+7  (f[t] <-> IN col jj0+t)
            float4 r0a = *reinterpret_cast<const float4*>(&IN[i + 2][jj0]);
            float4 r0b = *reinterpret_cast<const float4*>(&IN[i + 2][jj0 + 4]);
            float4 r1a = *reinterpret_cast<const float4*>(&IN[i + 3][jj0]);
            float4 r1b = *reinterpret_cast<const float4*>(&IN[i + 3][jj0 + 4]);
            float4 r2a = *reinterpret_cast<const float4*>(&IN[i + 4][jj0]);
            float4 r2b = *reinterpret_cast<const float4*>(&IN[i + 4][jj0 + 4]);
            float s[8], ctr[8];
            s[0] = r0a.x + r1a.x + r2a.x; ctr[0] = r1a.x;
            s[1] = r0a.y + r1a.y + r2a.y; ctr[1] = r1a.y;
            s[2] = r0a.z + r1a.z + r2a.z; ctr[2] = r1a.z;
            s[3] = r0a.w + r1a.w + r2a.w; ctr[3] = r1a.w;
            s[4] = r0b.x + r1b.x + r2b.x; ctr[4] = r1b.x;
            s[5] = r0b.y + r1b.y + r2b.y; ctr[5] = r1b.y;
            s[6] = r0b.z + r1b.z + r2b.z; ctr[6] = r1b.z;
            s[7] = r0b.w + r1b.w + r2b.w; ctr[7] = r1b.w;
            int gy = ty0 - 1 + i;
            float cy3 = cntk(gy, 1);
            float4 bp = make_float4(0.f, 0.f, 0.f, 0.f);
            float* bpe = reinterpret_cast<float*>(&bp);
            if ((unsigned)gy < HW) {
                #pragma unroll
                for (int oo = 0; oo < 4; oo++) {
                    int gx = tx0 - 1 + jj0 + oo;
                    if ((unsigned)gx < HW) {
                        float sum3 = s[oo + 2] + s[oo + 3] + s[oo + 4];
                        float r3 = __frcp_rn(cntk(gx, 1) * cy3);
                        bpe[oo] = ctr[oo + 3] - sum3 * r3;
                    }
                }
            }
            *reinterpret_cast<float4*>(&BP[i][jj0]) = bp;
        }
        __syncthreads();
        // Stage B: 3x3 conv over BP
        float wv[9];
        #pragma unroll
        for (int i = 0; i < 9; i++) wv[i] = __ldg(&w_hf[j * 9 + i]);
        float a0 = 0.f, a1 = 0.f, a2 = 0.f, a3 = 0.f;
        #pragma unroll
        for (int dy = 0; dy < 3; dy++) {
            float4 va = *reinterpret_cast<const float4*>(&BP[ly + dy][lx4]);
            float4 vb = *reinterpret_cast<const float4*>(&BP[ly + dy][lx4 + 4]);
            float f[8] = {va.x, va.y, va.z, va.w, vb.x, vb.y, vb.z, vb.w};
            #pragma unroll
            for (int t = 0; t < 3; t++) {
                float w = wv[dy * 3 + t];
                a0 = fmaf(f[0 + t], w, a0);
                a1 = fmaf(f[1 + t], w, a1);
                a2 = fmaf(f[2 + t], w, a2);
                a3 = fmaf(f[3 + t], w, a3);
            }
        }
        float4 r;
        r.x = silu_bn(a0, inv, bias);
        r.y = silu_bn(a1, inv, bias);
        r.z = silu_bn(a2, inv, bias);
        r.w = silu_bn(a3, inv, bias);
        *reinterpret_cast<float4*>(outp + (ty0 + ly) * HW + tx0 + lx4) = r;
    }
}

extern "C" void kernel_launch(void* const* d_in, const int* in_sizes, int n_in,
                              void* d_out, int out_size) {
    const float* x        = (const float*)d_in[0];
    const float* w_lo     = (const float*)d_in[1];
    const float* w_mf     = (const float*)d_in[2];
    const float* w_hf     = (const float*)d_in[3];
    const float* bn_gamma = (const float*)d_in[4];
    const float* bn_beta  = (const float*)d_in[5];
    const float* bn_mean  = (const float*)d_in[6];
    const float* bn_var   = (const float*)d_in[7];
    float* out = (float*)d_out;

    dim3 grid((HW / TILE) * (HW / TILE), 8 * CTOT);
    trifreq_kernel<<<grid, 256>>>(x, w_lo, w_mf, w_hf,
                                  bn_gamma, bn_beta, bn_mean, bn_var, out);
}